// round 4
// baseline (speedup 1.0000x reference)
#include <cuda_runtime.h>
#include <math.h>

#define BATCH 16
#define NA 3
#define NC 80
#define NCH 85
#define NT 512
#define THRESH 0.6f
#define EPSF 1e-7f

#define N0 307200
#define N1 76800
#define N2 19200

#define NBLK 148
#define NTHR 512
#define GSIZE (NBLK * NTHR)        // 75776

// float4 counts
#define PL0 1600
#define PL1 400
#define PL2 100
#define T0 76800
#define T1 19200
#define T2 4800

#define NPAIR 1536                  // 3 * 512
#define NLCLS (NPAIR * NC)          // 122880

__device__ double g_base[3];
__device__ double g_lcls[3];
__device__ double g_lbox[3];
__device__ double g_corr[3];
__device__ double g_nb[3];
__device__ unsigned g_done = 0;

__device__ __forceinline__ float softplus_fast(float x) {
    return fmaxf(x, 0.0f) + __logf(1.0f + __expf(-fabsf(x)));
}

__device__ __forceinline__ double warp_red(double v) {
#pragma unroll
    for (int o = 16; o > 0; o >>= 1)
        v += __shfl_down_sync(0xffffffffu, v, o);
    return v;
}

__global__ void __launch_bounds__(NTHR)
yolo_fused(const float* __restrict__ p0,
           const float* __restrict__ p1,
           const float* __restrict__ p2,
           const float* __restrict__ targets,
           const float* __restrict__ anchors,
           const float* __restrict__ image_size,
           float* __restrict__ out)
{
    __shared__ int      s_cell[3][NT];
    __shared__ unsigned s_off[3][NT];
    __shared__ float4   s_tgt[NT];
    __shared__ int      s_cls[NT];
    __shared__ double   s_red[16][6];

    int tid  = threadIdx.x;
    int blk  = blockIdx.x;
    int lane = tid & 31;
    int wid  = tid >> 5;
    int gt   = blk * NTHR + tid;

    float im0 = image_size[0];
    float im1 = image_size[1];

    // ---------------- metadata: thread tid handles target tid (all scales) ----------------
    {
        const float* tg = targets + tid * 6;
        float tb = tg[0];
        float tc = tg[1];
        float x  = tg[2], y = tg[3], w = tg[4], h = tg[5];
        s_tgt[tid] = make_float4(x, y, w, h);
        s_cls[tid] = (int)tc - 1;

#pragma unroll
        for (int s = 0; s < 3; s++) {
            int H = (s == 0) ? 80 : ((s == 1) ? 40 : 20);
            int W = H;
            float st0 = im0 / (float)H;
            float st1 = im1 / (float)W;

            float gx = x / st1, gy = y / st0;
            float gw = w / st1, gh = h / st0;

            float best = -1e30f;
            int arg = 0;
#pragma unroll
            for (int a = 0; a < 3; a++) {
                float aw = anchors[(s * 3 + a) * 2 + 0] / st1;
                float ah = anchors[(s * 3 + a) * 2 + 1] / st0;
                float inter = fminf(aw, gw) * fminf(ah, gh);
                float uni   = aw * ah + gw * gh - inter;
                float iou   = inter / uni;
                if (iou > best) { best = iou; arg = a; }
            }

            if (best > THRESH) {
                int b  = (int)tb;
                int gi = (int)gx;
                int gj = (int)gy;
                if (b  < 0) b  = 0; if (b  > BATCH - 1) b  = BATCH - 1;
                if (gi < 0) gi = 0; if (gi > W - 1)     gi = W - 1;
                if (gj < 0) gj = 0; if (gj > H - 1)     gj = H - 1;
                int cell = ((b * NA + arg) * H + gj) * W + gi;
                unsigned off = (unsigned)((b * NA + arg) * NCH) * (unsigned)(H * W)
                             + (unsigned)(gj * W + gi);
                s_cell[s][tid] = cell;
                s_off[s][tid]  = off | ((unsigned)arg << 28);
            } else {
                s_cell[s][tid] = -1;
                s_off[s][tid]  = 0u;
            }
        }
    }
    __syncthreads();

    // ---------------- objectness base BCE (4 independent predicated loads) ----------------
    const float4* p0v = reinterpret_cast<const float4*>(p0);
    const float4* p1v = reinterpret_cast<const float4*>(p1);
    const float4* p2v = reinterpret_cast<const float4*>(p2);

    int i0b = gt + GSIZE;
    bool h0b = i0b < T0;       // gt < 1024 (warp aligned)
    bool h1  = gt < T1;        // 19200
    bool h2  = gt < T2;        // 4800

    int ba0a = gt  / PL0;
    int ba0b = i0b / PL0;
    int ba1  = gt  / PL1;
    int ba2  = gt  / PL2;

    float4 va = p0v[(size_t)(ba0a * NCH + 4) * PL0 + (gt  - ba0a * PL0)];
    float4 vb = h0b ? p0v[(size_t)(ba0b * NCH + 4) * PL0 + (i0b - ba0b * PL0)]
                    : make_float4(0.f, 0.f, 0.f, 0.f);
    float4 vc = h1  ? p1v[(size_t)(ba1 * NCH + 4) * PL1 + (gt - ba1 * PL1)]
                    : make_float4(0.f, 0.f, 0.f, 0.f);
    float4 vd = h2  ? p2v[(size_t)(ba2 * NCH + 4) * PL2 + (gt - ba2 * PL2)]
                    : make_float4(0.f, 0.f, 0.f, 0.f);

    // ---------------- lcls: two distributed gather layers ----------------
    // layer A: item = gt (always < 122880)
    double lcA = 0.0;
    int sA;
    {
        int item = gt;
        int p = item / NC;
        int j = item - p * NC;
        sA = p >> 9;
        int t = p & 511;
        if (s_cell[sA][t] >= 0) {
            unsigned off = s_off[sA][t] & 0x0FFFFFFFu;
            int HW = (sA == 0) ? 6400 : ((sA == 1) ? 1600 : 400);
            const float* pis = (sA == 0) ? p0 : ((sA == 1) ? p1 : p2);
            float x = pis[off + (unsigned)(5 + j) * (unsigned)HW];
            lcA = (double)(softplus_fast(x) - ((j == s_cls[t]) ? x : 0.0f));
        }
    }
    // layer B: item = gt + GSIZE, active for gt < 47104 (warp aligned)
    double lcB = 0.0;
    int sB = 2;
    bool hB = (gt + GSIZE) < NLCLS;
    if (hB) {
        int item = gt + GSIZE;
        int p = item / NC;
        int j = item - p * NC;
        sB = p >> 9;
        int t = p & 511;
        if (s_cell[sB][t] >= 0) {
            unsigned off = s_off[sB][t] & 0x0FFFFFFFu;
            int HW = (sB == 0) ? 6400 : ((sB == 1) ? 1600 : 400);
            const float* pis = (sB == 0) ? p0 : ((sB == 1) ? p1 : p2);
            float x = pis[off + (unsigned)(5 + j) * (unsigned)HW];
            lcB = (double)(softplus_fast(x) - ((j == s_cls[t]) ? x : 0.0f));
        }
    }

    // ---------------- pair work: GIoU + dedup corr (first 1536 threads) ----------------
    if (gt < NPAIR) {
        int s = gt >> 9;            // warp uniform
        int t = gt & 511;
        double lb = 0.0, cr = 0.0, nbv = 0.0;

        int cell = s_cell[s][t];
        if (cell >= 0) {
            nbv = 1.0;

            // ownership: first target index owning this cell applies the correction
            bool owner = true;
            for (int u = 0; u < t; u++) {
                if (s_cell[s][u] == cell) { owner = false; break; }
            }

            unsigned packed = s_off[s][t];
            unsigned off = packed & 0x0FFFFFFFu;
            int a_s = (int)(packed >> 28);

            int H = (s == 0) ? 80 : ((s == 1) ? 40 : 20);
            int HW = H * H;
            const float* pis = (s == 0) ? p0 : ((s == 1) ? p1 : p2);
            float st0 = im0 / (float)H;
            float st1 = im1 / (float)H;

            float4 tg4 = s_tgt[t];
            float gx = tg4.x / st1, gy = tg4.y / st0;
            float gw = tg4.z / st1, gh = tg4.w / st0;
            float aw = anchors[(s * 3 + a_s) * 2 + 0] / st1;
            float ah = anchors[(s * 3 + a_s) * 2 + 1] / st0;

            float ps0 = pis[off];
            float ps1 = pis[off + HW];
            float ps2 = pis[off + 2 * HW];
            float ps3 = pis[off + 3 * HW];
            float lg  = pis[off + 4 * HW];

            float pcx = 1.0f / (1.0f + __expf(-ps0));
            float pcy = 1.0f / (1.0f + __expf(-ps1));
            float pw  = fminf(__expf(ps2), 1000.0f) * aw;
            float ph  = fminf(__expf(ps3), 1000.0f) * ah;

            float tcx = gx - floorf(gx);
            float tcy = gy - floorf(gy);

            float px1 = pcx - pw * 0.5f, py1 = pcy - ph * 0.5f;
            float px2 = pcx + pw * 0.5f, py2 = pcy + ph * 0.5f;
            float tx1 = tcx - gw * 0.5f, ty1 = tcy - gh * 0.5f;
            float tx2 = tcx + gw * 0.5f, ty2 = tcy + gh * 0.5f;

            float iw = fmaxf(fminf(px2, tx2) - fmaxf(px1, tx1), 0.0f);
            float ih = fmaxf(fminf(py2, ty2) - fmaxf(py1, ty1), 0.0f);
            float inter = iw * ih;
            float uni   = pw * ph + gw * gh - inter + EPSF;
            float iou   = inter / uni;
            float cw = fmaxf(px2, tx2) - fminf(px1, tx1);
            float ch = fmaxf(py2, ty2) - fminf(py1, ty1);
            float c_area = cw * ch + EPSF;
            float giou = iou - (c_area - uni) / c_area;

            lb = (double)(1.0f - giou);
            if (owner) cr = -(double)lg;
        }

        lb  = warp_red(lb);
        cr  = warp_red(cr);
        nbv = warp_red(nbv);
        if (lane == 0) {
            atomicAdd(&g_lbox[s], lb);
            atomicAdd(&g_corr[s], cr);
            atomicAdd(&g_nb[s],   nbv);
        }
    }

    // ---------------- objectness softplus + warp reductions ----------------
    double l0 = (double)(softplus_fast(va.x) + softplus_fast(va.y) +
                         softplus_fast(va.z) + softplus_fast(va.w));
    if (h0b) l0 += (double)(softplus_fast(vb.x) + softplus_fast(vb.y) +
                            softplus_fast(vb.z) + softplus_fast(vb.w));
    double l1 = h1 ? (double)(softplus_fast(vc.x) + softplus_fast(vc.y) +
                              softplus_fast(vc.z) + softplus_fast(vc.w)) : 0.0;
    double l2 = h2 ? (double)(softplus_fast(vd.x) + softplus_fast(vd.y) +
                              softplus_fast(vd.z) + softplus_fast(vd.w)) : 0.0;

    l0  = warp_red(l0);
    l1  = warp_red(l1);
    l2  = warp_red(l2);
    lcA = warp_red(lcA);
    lcB = warp_red(lcB);

    if (lane == 0) {
        double row[6] = { l0, l1, l2, 0.0, 0.0, 0.0 };
        row[3 + sA] += lcA;                 // sA warp uniform
        if (hB) row[3 + sB] += lcB;         // sB warp uniform
#pragma unroll
        for (int k = 0; k < 6; k++) s_red[wid][k] = row[k];
    }
    __syncthreads();

    if (wid < 6) {
        double v = (lane < 16) ? s_red[lane][wid] : 0.0;
        v = warp_red(v);
        if (lane == 0) {
            if (wid < 3) atomicAdd(&g_base[wid], v);
            else         atomicAdd(&g_lcls[wid - 3], v);
        }
    }

    // ---------------- finisher ----------------
    __syncthreads();
    if (tid == 0) {
        __threadfence();
        unsigned old = atomicAdd(&g_done, 1u);
        if (old == NBLK - 1) {
            __threadfence();
            const double counts[3] = { (double)N0, (double)N1, (double)N2 };
            double lbox = 0.0, lobj = 0.0, lcls = 0.0;
#pragma unroll
            for (int i = 0; i < 3; i++) {
                double nbv = g_nb[i] > 1.0 ? g_nb[i] : 1.0;
                lbox += g_lbox[i] / nbv;
                lcls += g_lcls[i] / (nbv * (double)NC);
                lobj += (g_base[i] + g_corr[i]) / counts[i];
            }
            lbox *= 3.54;
            lobj *= 64.3;
            lcls *= 37.4;
            out[0] = (float)(lbox + lobj + lcls);
            out[1] = (float)lbox;
            out[2] = (float)lobj;
            out[3] = (float)lcls;
#pragma unroll
            for (int i = 0; i < 3; i++) {
                g_base[i] = 0.0; g_lcls[i] = 0.0; g_lbox[i] = 0.0;
                g_corr[i] = 0.0; g_nb[i] = 0.0;
            }
            g_done = 0u;
            __threadfence();
        }
    }
}

extern "C" void kernel_launch(void* const* d_in, const int* in_sizes, int n_in,
                              void* d_out, int out_size) {
    const float* p0         = (const float*)d_in[0];
    const float* p1         = (const float*)d_in[1];
    const float* p2         = (const float*)d_in[2];
    const float* targets    = (const float*)d_in[3];
    const float* anchors    = (const float*)d_in[4];
    const float* image_size = (const float*)d_in[5];
    float* out = (float*)d_out;

    yolo_fused<<<NBLK, NTHR>>>(p0, p1, p2, targets, anchors, image_size, out);
}

// round 5
// speedup vs baseline: 1.3176x; 1.3176x over previous
#include <cuda_runtime.h>
#include <math.h>

#define BATCH 16
#define NA 3
#define NC 80
#define NCH 85
#define NT 512
#define THRESH 0.6f
#define EPSF 1e-7f

#define N0 307200
#define N1 76800
#define N2 19200

#define NBLK 148
#define NTHR 512
#define OBJ_BLKS (NBLK - 3)
#define GSTRIDE (OBJ_BLKS * NTHR)   // 74240

#define PL0 1600
#define PL1 400
#define PL2 100
#define T0 76800
#define T1 19200
#define T2 4800

__device__ double g_lbox[3];
__device__ double g_lcls[3];
__device__ double g_nb[3];
__device__ double g_corr[3];
__device__ double g_base[3];
__device__ unsigned g_done = 0;

__device__ __forceinline__ float softplus_fast(float x) {
    return fmaxf(x, 0.0f) + __logf(1.0f + __expf(-fabsf(x)));
}

__device__ __forceinline__ double warp_red(double v) {
#pragma unroll
    for (int o = 16; o > 0; o >>= 1)
        v += __shfl_down_sync(0xffffffffu, v, o);
    return v;
}

__global__ void __launch_bounds__(NTHR)
yolo_fused(const float* __restrict__ p0,
           const float* __restrict__ p1,
           const float* __restrict__ p2,
           const float* __restrict__ targets,
           const float* __restrict__ anchors,
           const float* __restrict__ image_size,
           float* __restrict__ out)
{
    __shared__ double sred[16][4];

    int tid  = threadIdx.x;
    int blk  = blockIdx.x;
    int lane = tid & 31;
    int wid  = tid >> 5;

    if (blk >= 3) {
        // ---------------- objectness base BCE ----------------
        int gid = (blk - 3) * NTHR + tid;

        const float4* p0v = reinterpret_cast<const float4*>(p0);
        const float4* p1v = reinterpret_cast<const float4*>(p1);
        const float4* p2v = reinterpret_cast<const float4*>(p2);

        int i0b = gid + GSTRIDE;
        bool h0b = i0b < T0;   // gid < 2560
        bool h1  = gid < T1;   // 19200
        bool h2  = gid < T2;   // 4800

        int ba0a = gid / PL0;
        int ba0b = i0b / PL0;
        int ba1  = gid / PL1;
        int ba2  = gid / PL2;

        float4 va = p0v[(size_t)(ba0a * NCH + 4) * PL0 + (gid - ba0a * PL0)];
        float4 vb = h0b ? p0v[(size_t)(ba0b * NCH + 4) * PL0 + (i0b - ba0b * PL0)]
                        : make_float4(0.f, 0.f, 0.f, 0.f);
        float4 vc = h1  ? p1v[(size_t)(ba1 * NCH + 4) * PL1 + (gid - ba1 * PL1)]
                        : make_float4(0.f, 0.f, 0.f, 0.f);
        float4 vd = h2  ? p2v[(size_t)(ba2 * NCH + 4) * PL2 + (gid - ba2 * PL2)]
                        : make_float4(0.f, 0.f, 0.f, 0.f);

        double l0 = (double)(softplus_fast(va.x) + softplus_fast(va.y) +
                             softplus_fast(va.z) + softplus_fast(va.w));
        if (h0b) l0 += (double)(softplus_fast(vb.x) + softplus_fast(vb.y) +
                                softplus_fast(vb.z) + softplus_fast(vb.w));
        double l1 = h1 ? (double)(softplus_fast(vc.x) + softplus_fast(vc.y) +
                                  softplus_fast(vc.z) + softplus_fast(vc.w)) : 0.0;
        double l2 = h2 ? (double)(softplus_fast(vd.x) + softplus_fast(vd.y) +
                                  softplus_fast(vd.z) + softplus_fast(vd.w)) : 0.0;

        // warp-uniform activity flags: skip dead shuffle chains
        int wbase = (blk - 3) * NTHR + (wid << 5);
        bool w1 = wbase < T1;
        bool w2 = wbase < T2;

        l0 = warp_red(l0);
        if (w1) l1 = warp_red(l1);
        if (w2) l2 = warp_red(l2);
        if (lane == 0) {
            sred[wid][0] = l0;
            sred[wid][1] = w1 ? l1 : 0.0;
            sred[wid][2] = w2 ? l2 : 0.0;
        }
        __syncthreads();
        if (wid < 3) {
            double a = (lane < 16) ? sred[lane][wid] : 0.0;
            a = warp_red(a);
            if (lane == 0) atomicAdd(&g_base[wid], a);
        }
    } else {
        // ---------------- target block for scale `blk` ----------------
        __shared__ int      table[1024];
        __shared__ unsigned s_off[NT];
        __shared__ int      s_cls[NT];
        __shared__ int      s_cnt;

        const float* pi;
        int H, W;
        if (blk == 0)      { pi = p0; H = 80; W = 80; }
        else if (blk == 1) { pi = p1; H = 40; W = 40; }
        else               { pi = p2; H = 20; W = 20; }
        int HW = H * W;

        float stride0 = image_size[0] / (float)H;
        float stride1 = image_size[1] / (float)W;

        float aw[3], ah[3];
#pragma unroll
        for (int a = 0; a < 3; a++) {
            aw[a] = anchors[(blk * 3 + a) * 2 + 0] / stride1;
            ah[a] = anchors[(blk * 3 + a) * 2 + 1] / stride0;
        }

        table[tid] = -1;
        table[tid + 512] = -1;
        if (tid == 0) s_cnt = 0;
        __syncthreads();

        double lbox = 0.0, nb = 0.0, corr = 0.0;

        {
            const float* tg = targets + tid * 6;
            float t0 = tg[0];
            float t1 = tg[1];
            float gx = tg[2] / stride1;
            float gy = tg[3] / stride0;
            float gw = tg[4] / stride1;
            float gh = tg[5] / stride0;

            float best = -1e30f;
            int arg = 0;
#pragma unroll
            for (int a = 0; a < 3; a++) {
                float inter = fminf(aw[a], gw) * fminf(ah[a], gh);
                float uni   = aw[a] * ah[a] + gw * gh - inter;
                float iou   = inter / uni;
                if (iou > best) { best = iou; arg = a; }
            }

            if (best > THRESH) {
                int b  = (int)t0;
                int c  = (int)t1;
                int gi = (int)gx;
                int gj = (int)gy;
                if (b  < 0) b  = 0; if (b  > BATCH - 1) b  = BATCH - 1;
                if (gi < 0) gi = 0; if (gi > W - 1)     gi = W - 1;
                if (gj < 0) gj = 0; if (gj > H - 1)     gj = H - 1;
                int a_s = arg;

                int cell = ((b * NA + a_s) * H + gj) * W + gi;
                unsigned off = (unsigned)((b * NA + a_s) * NCH) * (unsigned)HW
                             + (unsigned)(gj * W + gi);

                // issue all 5 gathers up-front (one latency wave)
                float ps0 = pi[off];
                float ps1 = pi[off + HW];
                float ps2 = pi[off + 2 * HW];
                float ps3 = pi[off + 3 * HW];
                float lg  = pi[off + 4 * HW];

                float pcx = 1.0f / (1.0f + __expf(-ps0));
                float pcy = 1.0f / (1.0f + __expf(-ps1));
                float pw  = fminf(__expf(ps2), 1000.0f) * aw[a_s];
                float ph  = fminf(__expf(ps3), 1000.0f) * ah[a_s];

                float tcx = gx - floorf(gx);
                float tcy = gy - floorf(gy);

                float px1 = pcx - pw * 0.5f, py1 = pcy - ph * 0.5f;
                float px2 = pcx + pw * 0.5f, py2 = pcy + ph * 0.5f;
                float tx1 = tcx - gw * 0.5f, ty1 = tcy - gh * 0.5f;
                float tx2 = tcx + gw * 0.5f, ty2 = tcy + gh * 0.5f;

                float iw = fmaxf(fminf(px2, tx2) - fmaxf(px1, tx1), 0.0f);
                float ih = fmaxf(fminf(py2, ty2) - fmaxf(py1, ty1), 0.0f);
                float inter = iw * ih;
                float uni   = pw * ph + gw * gh - inter + EPSF;
                float iou   = inter / uni;
                float cw = fmaxf(px2, tx2) - fminf(px1, tx1);
                float ch = fmaxf(py2, ty2) - fminf(py1, ty1);
                float c_area = cw * ch + EPSF;
                float giou = iou - (c_area - uni) / c_area;

                lbox = (double)(1.0f - giou);
                nb   = 1.0;

                unsigned h = ((unsigned)cell * 2654435761u) & 1023u;
                bool owner = false;
                while (true) {
                    int prev = atomicCAS(&table[h], -1, cell);
                    if (prev == -1)   { owner = true; break; }
                    if (prev == cell) { break; }
                    h = (h + 1) & 1023u;
                }
                if (owner) corr = -(double)lg;

                int slot = atomicAdd(&s_cnt, 1);
                s_off[slot] = off;
                s_cls[slot] = c - 1;
            }
        }
        __syncthreads();

        // cooperative class-BCE, unrolled for MLP
        int cnt  = s_cnt;
        int nitm = cnt * NC;
        double lcls = 0.0;
#pragma unroll 8
        for (int k = tid; k < nitm; k += NTHR) {
            int idx = k / NC;
            int j   = k - idx * NC;
            float x = pi[s_off[idx] + (unsigned)(5 + j) * (unsigned)HW];
            lcls += (double)(softplus_fast(x) - ((j == s_cls[idx]) ? x : 0.0f));
        }

        lbox = warp_red(lbox);
        nb   = warp_red(nb);
        corr = warp_red(corr);
        lcls = warp_red(lcls);
        if (lane == 0) {
            sred[wid][0] = lbox; sred[wid][1] = nb;
            sred[wid][2] = corr; sred[wid][3] = lcls;
        }
        __syncthreads();
        if (wid < 4) {
            double a = (lane < 16) ? sred[lane][wid] : 0.0;
            a = warp_red(a);
            if (lane == 0) {
                if      (wid == 0) g_lbox[blk] = a;
                else if (wid == 1) g_nb[blk]   = a;
                else if (wid == 2) g_corr[blk] = a;
                else               g_lcls[blk] = a;
            }
        }
    }

    // ---------------- finisher ----------------
    __syncthreads();
    if (tid == 0) {
        __threadfence();
        unsigned old = atomicAdd(&g_done, 1u);
        if (old == NBLK - 1) {
            __threadfence();
            const double counts[3] = { (double)N0, (double)N1, (double)N2 };
            double lbox = 0.0, lobj = 0.0, lcls = 0.0;
#pragma unroll
            for (int i = 0; i < 3; i++) {
                double nbv = g_nb[i] > 1.0 ? g_nb[i] : 1.0;
                lbox += g_lbox[i] / nbv;
                lcls += g_lcls[i] / (nbv * (double)NC);
                lobj += (g_base[i] + g_corr[i]) / counts[i];
            }
            lbox *= 3.54;
            lobj *= 64.3;
            lcls *= 37.4;
            out[0] = (float)(lbox + lobj + lcls);
            out[1] = (float)lbox;
            out[2] = (float)lobj;
            out[3] = (float)lcls;
#pragma unroll
            for (int i = 0; i < 3; i++) {
                g_lbox[i] = 0.0; g_lcls[i] = 0.0; g_nb[i] = 0.0;
                g_corr[i] = 0.0; g_base[i] = 0.0;
            }
            g_done = 0u;
            __threadfence();
        }
    }
}

extern "C" void kernel_launch(void* const* d_in, const int* in_sizes, int n_in,
                              void* d_out, int out_size) {
    const float* p0         = (const float*)d_in[0];
    const float* p1         = (const float*)d_in[1];
    const float* p2         = (const float*)d_in[2];
    const float* targets    = (const float*)d_in[3];
    const float* anchors    = (const float*)d_in[4];
    const float* image_size = (const float*)d_in[5];
    float* out = (float*)d_out;

    yolo_fused<<<NBLK, NTHR>>>(p0, p1, p2, targets, anchors, image_size, out);
}

// round 6
// speedup vs baseline: 2.2741x; 1.7259x over previous
#include <cuda_runtime.h>
#include <math.h>

#define BATCH 16
#define NA 3
#define NC 80
#define NCH 85
#define NT 512
#define THRESH 0.6f
#define EPSF 1e-7f

#define N0 307200
#define N1 76800
#define N2 19200

#define NBLK 148
#define NTHR 512
#define GSIZE (NBLK * NTHR)     // 75776

#define PL0 1600
#define PL1 400
#define PL2 100
#define T0 76800
#define T1 19200
#define T2 4800

#define NLCLS 122880            // 3*512*80
#define HB_LIMIT (NLCLS - GSIZE) // 47104, multiple of 512

#define W0 (1.0f / (float)N0)
#define W1 (1.0f / (float)N1)
#define W2 (1.0f / (float)N2)

__device__ float g_obj;        // sum_s (base_s + corr_s)/count_s
__device__ float g_lcls[3];
__device__ float g_lbox[3];
__device__ float g_nb[3];
__device__ unsigned g_done = 0;

__device__ __forceinline__ float softplus_fast(float x) {
    return fmaxf(x, 0.0f) + __logf(1.0f + __expf(-fabsf(x)));
}

__device__ __forceinline__ float sp4(float4 v) {
    return softplus_fast(v.x) + softplus_fast(v.y) +
           softplus_fast(v.z) + softplus_fast(v.w);
}

__device__ __forceinline__ float warp_red_f(float v) {
#pragma unroll
    for (int o = 16; o > 0; o >>= 1)
        v += __shfl_down_sync(0xffffffffu, v, o);
    return v;
}

__global__ void __launch_bounds__(NTHR)
yolo_fused(const float* __restrict__ p0,
           const float* __restrict__ p1,
           const float* __restrict__ p2,
           const float* __restrict__ targets,
           const float* __restrict__ anchors,
           const float* __restrict__ image_size,
           float* __restrict__ out)
{
    __shared__ int      s_cell[3][NT];
    __shared__ unsigned s_offp[3][NT];
    __shared__ int      s_cls[NT];
    __shared__ float    s_red[16][6];
    __shared__ int      table[1024];

    int tid  = threadIdx.x;
    int blk  = blockIdx.x;
    int lane = tid & 31;
    int wid  = tid >> 5;
    int gt   = blk * NTHR + tid;

    // ---------- issue objectness loads immediately (independent) ----------
    const float4* p0v = reinterpret_cast<const float4*>(p0);
    const float4* p1v = reinterpret_cast<const float4*>(p1);
    const float4* p2v = reinterpret_cast<const float4*>(p2);

    int  i0b = gt + GSIZE;
    bool h0b = i0b < T0;       // gt < 1024
    bool h1  = gt < T1;
    bool h2  = gt < T2;

    int ba0a = gt  / PL0;
    int ba0b = i0b / PL0;
    int ba1  = gt  / PL1;
    int ba2  = gt  / PL2;

    float4 va = p0v[(size_t)(ba0a * NCH + 4) * PL0 + (gt  - ba0a * PL0)];
    float4 vb = h0b ? p0v[(size_t)(ba0b * NCH + 4) * PL0 + (i0b - ba0b * PL0)]
                    : make_float4(0.f, 0.f, 0.f, 0.f);
    float4 vc = h1  ? p1v[(size_t)(ba1 * NCH + 4) * PL1 + (gt - ba1 * PL1)]
                    : make_float4(0.f, 0.f, 0.f, 0.f);
    float4 vd = h2  ? p2v[(size_t)(ba2 * NCH + 4) * PL2 + (gt - ba2 * PL2)]
                    : make_float4(0.f, 0.f, 0.f, 0.f);

    // ---------- metadata for all 512 targets x 3 scales (every block) ----------
    if (blk < 3) { table[tid] = -1; table[tid + 512] = -1; }

    float im0 = image_size[0];
    float im1 = image_size[1];
    {
        const float* tg = targets + tid * 6;
        float tb = tg[0];
        float tc = tg[1];
        float x = tg[2], y = tg[3], w = tg[4], h = tg[5];
        s_cls[tid] = (int)tc - 1;

#pragma unroll
        for (int s = 0; s < 3; s++) {
            int   H   = (s == 0) ? 80 : ((s == 1) ? 40 : 20);
            float inv0 = (float)H / im0;      // 1/stride0
            float inv1 = (float)H / im1;      // 1/stride1

            float gw = w * inv1, gh = h * inv0;

            // anchor argmax via cross-multiplication (no divides)
            float bi = -1.0f, bu = 1.0f;      // best inter/union
            int arg = 0;
#pragma unroll
            for (int a = 0; a < 3; a++) {
                float aw = anchors[(s * 3 + a) * 2 + 0] * inv1;
                float ah = anchors[(s * 3 + a) * 2 + 1] * inv0;
                float inter = fminf(aw, gw) * fminf(ah, gh);
                float uni   = aw * ah + gw * gh - inter;
                if (inter * bu > bi * uni) { bi = inter; bu = uni; arg = a; }
            }

            if (bi > THRESH * bu) {
                float gx = x * inv1, gy = y * inv0;
                int b  = (int)tb;
                int gi = (int)gx;
                int gj = (int)gy;
                if (b  < 0) b  = 0; if (b  > BATCH - 1) b  = BATCH - 1;
                if (gi < 0) gi = 0; if (gi > H - 1)     gi = H - 1;
                if (gj < 0) gj = 0; if (gj > H - 1)     gj = H - 1;
                int cell = ((b * NA + arg) * H + gj) * H + gi;
                unsigned off = (unsigned)((b * NA + arg) * NCH) * (unsigned)(H * H)
                             + (unsigned)(gj * H + gi);
                s_cell[s][tid] = cell;
                s_offp[s][tid] = off | ((unsigned)arg << 28);
            } else {
                s_cell[s][tid] = -1;
                s_offp[s][tid] = 0u;
            }
        }
    }
    __syncthreads();

    // ---------- lcls: two distributed gather layers over all blocks ----------
    float lcA = 0.0f, lcB = 0.0f;
    int sA, sB = 2;
    bool hB = gt < HB_LIMIT;   // warp uniform
    {
        int p = gt / NC;
        int j = gt - p * NC;
        sA = p >> 9;
        int t = p & 511;
        if (s_cell[sA][t] >= 0) {
            unsigned off = s_offp[sA][t] & 0x0FFFFFFFu;
            int HW = (sA == 0) ? 6400 : ((sA == 1) ? 1600 : 400);
            const float* pis = (sA == 0) ? p0 : ((sA == 1) ? p1 : p2);
            float x = pis[off + (unsigned)(5 + j) * (unsigned)HW];
            lcA = softplus_fast(x) - ((j == s_cls[t]) ? x : 0.0f);
        }
    }
    if (hB) {
        int item = gt + GSIZE;
        int p = item / NC;
        int j = item - p * NC;
        sB = p >> 9;
        int t = p & 511;
        if (s_cell[sB][t] >= 0) {
            unsigned off = s_offp[sB][t] & 0x0FFFFFFFu;
            int HW = (sB == 0) ? 6400 : ((sB == 1) ? 1600 : 400);
            const float* pis = (sB == 0) ? p0 : ((sB == 1) ? p1 : p2);
            float x = pis[off + (unsigned)(5 + j) * (unsigned)HW];
            lcB = softplus_fast(x) - ((j == s_cls[t]) ? x : 0.0f);
        }
    }

    // ---------- weighted objectness accumulation (single scalar) ----------
    float obj = W0 * sp4(va);
    if (h0b) obj += W0 * sp4(vb);
    if (h1)  obj += W1 * sp4(vc);
    if (h2)  obj += W2 * sp4(vd);

    // ---------- pair work: GIoU + dedup corr (blocks 0-2 only) ----------
    float lbox = 0.0f, nb = 0.0f;
    if (blk < 3) {
        int s = blk, t = tid;
        int cell = s_cell[s][t];
        if (cell >= 0) {
            nb = 1.0f;
            unsigned packed = s_offp[s][t];
            unsigned off = packed & 0x0FFFFFFFu;
            int a_s = (int)(packed >> 28);

            int   H   = (s == 0) ? 80 : ((s == 1) ? 40 : 20);
            int   HW  = H * H;
            const float* pis = (s == 0) ? p0 : ((s == 1) ? p1 : p2);
            float inv0 = (float)H / im0;
            float inv1 = (float)H / im1;
            float ws   = (s == 0) ? W0 : ((s == 1) ? W1 : W2);

            const float* tg = targets + t * 6;
            float gx = tg[2] * inv1, gy = tg[3] * inv0;
            float gw = tg[4] * inv1, gh = tg[5] * inv0;
            float aw = anchors[(s * 3 + a_s) * 2 + 0] * inv1;
            float ah = anchors[(s * 3 + a_s) * 2 + 1] * inv0;

            float ps0 = pis[off];
            float ps1 = pis[off + HW];
            float ps2 = pis[off + 2 * HW];
            float ps3 = pis[off + 3 * HW];
            float lg  = pis[off + 4 * HW];

            float pcx = 1.0f / (1.0f + __expf(-ps0));
            float pcy = 1.0f / (1.0f + __expf(-ps1));
            float pw  = fminf(__expf(ps2), 1000.0f) * aw;
            float ph  = fminf(__expf(ps3), 1000.0f) * ah;

            float tcx = gx - floorf(gx);
            float tcy = gy - floorf(gy);

            float px1 = pcx - pw * 0.5f, py1 = pcy - ph * 0.5f;
            float px2 = pcx + pw * 0.5f, py2 = pcy + ph * 0.5f;
            float tx1 = tcx - gw * 0.5f, ty1 = tcy - gh * 0.5f;
            float tx2 = tcx + gw * 0.5f, ty2 = tcy + gh * 0.5f;

            float iw = fmaxf(fminf(px2, tx2) - fmaxf(px1, tx1), 0.0f);
            float ih = fmaxf(fminf(py2, ty2) - fmaxf(py1, ty1), 0.0f);
            float inter = iw * ih;
            float uni   = pw * ph + gw * gh - inter + EPSF;
            float iou   = inter / uni;
            float cw = fmaxf(px2, tx2) - fminf(px1, tx1);
            float ch = fmaxf(py2, ty2) - fminf(py1, ty1);
            float c_area = cw * ch + EPSF;
            float giou = iou - (c_area - uni) / c_area;

            lbox = 1.0f - giou;

            unsigned hsh = ((unsigned)cell * 2654435761u) & 1023u;
            bool owner = false;
            while (true) {
                int prev = atomicCAS(&table[hsh], -1, cell);
                if (prev == -1)   { owner = true; break; }
                if (prev == cell) { break; }
                hsh = (hsh + 1) & 1023u;
            }
            if (owner) obj += -lg * ws;    // folded tobj correction
        }
    }

    // ---------- reductions (all float) ----------
    obj = warp_red_f(obj);
    lcA = warp_red_f(lcA);
    if (hB) lcB = warp_red_f(lcB);
    bool isTgt = (blk < 3);
    if (isTgt) { lbox = warp_red_f(lbox); nb = warp_red_f(nb); }

    if (lane == 0) {
        float row0 = obj;
        float row1 = 0.f, row2 = 0.f, row3 = 0.f;
        if      (sA == 0) row1 += lcA;
        else if (sA == 1) row2 += lcA;
        else              row3 += lcA;
        if (hB) {
            if      (sB == 0) row1 += lcB;
            else if (sB == 1) row2 += lcB;
            else              row3 += lcB;
        }
        s_red[wid][0] = row0;
        s_red[wid][1] = row1;
        s_red[wid][2] = row2;
        s_red[wid][3] = row3;
        s_red[wid][4] = isTgt ? lbox : 0.f;
        s_red[wid][5] = isTgt ? nb   : 0.f;
    }
    __syncthreads();

    if (wid < 6) {
        float v = (lane < 16) ? s_red[lane][wid] : 0.0f;
        v = warp_red_f(v);
        if (lane == 0) {
            if      (wid == 0) atomicAdd(&g_obj, v);
            else if (wid <  4) atomicAdd(&g_lcls[wid - 1], v);
            else if (blk < 3) {
                if (wid == 4) g_lbox[blk] = v;   // single writer per scale
                else          g_nb[blk]   = v;
            }
        }
    }

    // ---------- finisher ----------
    __syncthreads();
    if (tid == 0) {
        __threadfence();
        unsigned old = atomicAdd(&g_done, 1u);
        if (old == NBLK - 1) {
            __threadfence();
            float lboxT = 0.f, lclsT = 0.f;
#pragma unroll
            for (int i = 0; i < 3; i++) {
                float nbv = fmaxf(g_nb[i], 1.0f);
                lboxT += g_lbox[i] / nbv;
                lclsT += g_lcls[i] / (nbv * (float)NC);
            }
            float lobjT = g_obj * 64.3f;
            lboxT *= 3.54f;
            lclsT *= 37.4f;
            out[0] = lboxT + lobjT + lclsT;
            out[1] = lboxT;
            out[2] = lobjT;
            out[3] = lclsT;
            g_obj = 0.f;
#pragma unroll
            for (int i = 0; i < 3; i++) {
                g_lcls[i] = 0.f; g_lbox[i] = 0.f; g_nb[i] = 0.f;
            }
            g_done = 0u;
            __threadfence();
        }
    }
}

extern "C" void kernel_launch(void* const* d_in, const int* in_sizes, int n_in,
                              void* d_out, int out_size) {
    const float* p0         = (const float*)d_in[0];
    const float* p1         = (const float*)d_in[1];
    const float* p2         = (const float*)d_in[2];
    const float* targets    = (const float*)d_in[3];
    const float* anchors    = (const float*)d_in[4];
    const float* image_size = (const float*)d_in[5];
    float* out = (float*)d_out;

    yolo_fused<<<NBLK, NTHR>>>(p0, p1, p2, targets, anchors, image_size, out);
}

// round 7
// speedup vs baseline: 2.8782x; 1.2657x over previous
#include <cuda_runtime.h>
#include <math.h>

#define BATCH 16
#define NA 3
#define NC 80
#define NCH 85
#define NT 512
#define THRESH 0.6f
#define EPSF 1e-7f

#define N0 307200
#define N1 76800
#define N2 19200

#define NBLK 296
#define NTHR 512

#define PL0 1600
#define PL1 400
#define PL2 100
#define T0 76800            // float4 items in p0 obj
#define TE1 96000           // T0 + 19200
#define TE2 100800          // TE1 + 4800

#define NLCLS 122880        // 3*512*80

#define W0 (1.0f / (float)N0)
#define W1 (1.0f / (float)N1)
#define W2 (1.0f / (float)N2)

__device__ float g_obj;
__device__ float g_lcls[3];
__device__ float g_lbox[3];
__device__ float g_nb[3];
__device__ unsigned g_done = 0;

__device__ __forceinline__ float softplus_fast(float x) {
    return fmaxf(x, 0.0f) + __logf(1.0f + __expf(-fabsf(x)));
}

__device__ __forceinline__ float sp4(float4 v) {
    return softplus_fast(v.x) + softplus_fast(v.y) +
           softplus_fast(v.z) + softplus_fast(v.w);
}

__device__ __forceinline__ float warp_red_f(float v) {
#pragma unroll
    for (int o = 16; o > 0; o >>= 1)
        v += __shfl_down_sync(0xffffffffu, v, o);
    return v;
}

// Per-(scale,target) metadata. Returns true if masked-in.
__device__ __forceinline__ bool target_meta(
    const float* __restrict__ targets, const float* __restrict__ anchors,
    float im0, float im1, int s, int t, int H,
    unsigned& off, int& cell, int& a_out,
    float& gx, float& gy, float& gw, float& gh)
{
    const float* tg = targets + t * 6;
    float inv0 = (float)H / im0;
    float inv1 = (float)H / im1;

    gw = tg[4] * inv1;
    gh = tg[5] * inv0;

    float bi = -1.0f, bu = 1.0f;
    int arg = 0;
#pragma unroll
    for (int a = 0; a < 3; a++) {
        float aw = anchors[(s * 3 + a) * 2 + 0] * inv1;
        float ah = anchors[(s * 3 + a) * 2 + 1] * inv0;
        float inter = fminf(aw, gw) * fminf(ah, gh);
        float uni   = aw * ah + gw * gh - inter;
        if (inter * bu > bi * uni) { bi = inter; bu = uni; arg = a; }
    }
    if (!(bi > THRESH * bu)) return false;

    gx = tg[2] * inv1;
    gy = tg[3] * inv0;
    int b  = (int)tg[0];
    int gi = (int)gx;
    int gj = (int)gy;
    if (b  < 0) b  = 0; if (b  > BATCH - 1) b  = BATCH - 1;
    if (gi < 0) gi = 0; if (gi > H - 1)     gi = H - 1;
    if (gj < 0) gj = 0; if (gj > H - 1)     gj = H - 1;
    cell  = ((b * NA + arg) * H + gj) * H + gi;
    off   = (unsigned)((b * NA + arg) * NCH) * (unsigned)(H * H)
          + (unsigned)(gj * H + gi);
    a_out = arg;
    return true;
}

__global__ void __launch_bounds__(NTHR, 2)
yolo_fused(const float* __restrict__ p0,
           const float* __restrict__ p1,
           const float* __restrict__ p2,
           const float* __restrict__ targets,
           const float* __restrict__ anchors,
           const float* __restrict__ image_size,
           float* __restrict__ out)
{
    __shared__ float s_red[16][6];
    __shared__ int   table[1024];

    int tid  = threadIdx.x;
    int blk  = blockIdx.x;
    int lane = tid & 31;
    int wid  = tid >> 5;
    int gt   = blk * NTHR + tid;

    float im0 = image_size[0];
    float im1 = image_size[1];

    // ---------------- objectness: <=1 float4 per thread ----------------
    const float4* p0v = reinterpret_cast<const float4*>(p0);
    const float4* p1v = reinterpret_cast<const float4*>(p1);
    const float4* p2v = reinterpret_cast<const float4*>(p2);

    float obj = 0.0f;
    if (gt < T0) {
        int ba = gt / PL0;
        int r  = gt - ba * PL0;
        obj = W0 * sp4(p0v[(size_t)(ba * NCH + 4) * PL0 + r]);
    } else if (gt < TE1) {
        int i  = gt - T0;
        int ba = i / PL1;
        int r  = i - ba * PL1;
        obj = W1 * sp4(p1v[(size_t)(ba * NCH + 4) * PL1 + r]);
    } else if (gt < TE2) {
        int i  = gt - TE1;
        int ba = i / PL2;
        int r  = i - ba * PL2;
        obj = W2 * sp4(p2v[(size_t)(ba * NCH + 4) * PL2 + r]);
    }

    // ---------------- lcls: one item per thread, inline metadata ----------------
    float lc = 0.0f;
    int sA = 2;
    if (gt < NLCLS) {
        int p = gt / NC;
        int j = gt - p * NC;
        sA = p >> 9;            // warp uniform
        int t = p & 511;
        int H = (sA == 0) ? 80 : ((sA == 1) ? 40 : 20);

        unsigned off; int cell, a_s; float gx, gy, gw, gh;
        if (target_meta(targets, anchors, im0, im1, sA, t, H,
                        off, cell, a_s, gx, gy, gw, gh)) {
            int HW = H * H;
            const float* pis = (sA == 0) ? p0 : ((sA == 1) ? p1 : p2);
            float x = pis[off + (unsigned)(5 + j) * (unsigned)HW];
            int cls = (int)targets[t * 6 + 1] - 1;
            lc = softplus_fast(x) - ((j == cls) ? x : 0.0f);
        }
    }

    // ---------------- pair work: blocks 0-2 only ----------------
    float lbox = 0.0f, nb = 0.0f;
    bool isTgt = (blk < 3);
    if (isTgt) {
        table[tid] = -1;
        table[tid + 512] = -1;
        __syncthreads();

        int s = blk, t = tid;
        int H = (s == 0) ? 80 : ((s == 1) ? 40 : 20);
        unsigned off; int cell, a_s; float gx, gy, gw, gh;
        if (target_meta(targets, anchors, im0, im1, s, t, H,
                        off, cell, a_s, gx, gy, gw, gh)) {
            nb = 1.0f;
            int HW = H * H;
            const float* pis = (s == 0) ? p0 : ((s == 1) ? p1 : p2);
            float inv0 = (float)H / im0;
            float inv1 = (float)H / im1;
            float ws   = (s == 0) ? W0 : ((s == 1) ? W1 : W2);

            float aw = anchors[(s * 3 + a_s) * 2 + 0] * inv1;
            float ah = anchors[(s * 3 + a_s) * 2 + 1] * inv0;

            float ps0 = pis[off];
            float ps1 = pis[off + HW];
            float ps2 = pis[off + 2 * HW];
            float ps3 = pis[off + 3 * HW];
            float lg  = pis[off + 4 * HW];

            float pcx = 1.0f / (1.0f + __expf(-ps0));
            float pcy = 1.0f / (1.0f + __expf(-ps1));
            float pw  = fminf(__expf(ps2), 1000.0f) * aw;
            float ph  = fminf(__expf(ps3), 1000.0f) * ah;

            float tcx = gx - floorf(gx);
            float tcy = gy - floorf(gy);

            float px1 = pcx - pw * 0.5f, py1 = pcy - ph * 0.5f;
            float px2 = pcx + pw * 0.5f, py2 = pcy + ph * 0.5f;
            float tx1 = tcx - gw * 0.5f, ty1 = tcy - gh * 0.5f;
            float tx2 = tcx + gw * 0.5f, ty2 = tcy + gh * 0.5f;

            float iw = fmaxf(fminf(px2, tx2) - fmaxf(px1, tx1), 0.0f);
            float ih = fmaxf(fminf(py2, ty2) - fmaxf(py1, ty1), 0.0f);
            float inter = iw * ih;
            float uni   = pw * ph + gw * gh - inter + EPSF;
            float iou   = inter / uni;
            float cw = fmaxf(px2, tx2) - fminf(px1, tx1);
            float ch = fmaxf(py2, ty2) - fminf(py1, ty1);
            float c_area = cw * ch + EPSF;
            float giou = iou - (c_area - uni) / c_area;

            lbox = 1.0f - giou;

            unsigned hsh = ((unsigned)cell * 2654435761u) & 1023u;
            bool owner = false;
            while (true) {
                int prev = atomicCAS(&table[hsh], -1, cell);
                if (prev == -1)   { owner = true; break; }
                if (prev == cell) { break; }
                hsh = (hsh + 1) & 1023u;
            }
            if (owner) obj += -lg * ws;   // folded tobj correction
        }
    }

    // ---------------- reductions (float, pairwise) ----------------
    obj = warp_red_f(obj);
    lc  = warp_red_f(lc);
    if (isTgt) { lbox = warp_red_f(lbox); nb = warp_red_f(nb); }

    if (lane == 0) {
        s_red[wid][0] = obj;
        s_red[wid][1] = (sA == 0) ? lc : 0.f;
        s_red[wid][2] = (sA == 1) ? lc : 0.f;
        s_red[wid][3] = (sA == 2) ? lc : 0.f;
        s_red[wid][4] = isTgt ? lbox : 0.f;
        s_red[wid][5] = isTgt ? nb   : 0.f;
    }
    __syncthreads();

    if (wid < 6) {
        float v = (lane < 16) ? s_red[lane][wid] : 0.0f;
        v = warp_red_f(v);
        if (lane == 0) {
            if      (wid == 0) atomicAdd(&g_obj, v);
            else if (wid <  4) { if (v != 0.0f) atomicAdd(&g_lcls[wid - 1], v); }
            else if (isTgt) {
                if (wid == 4) g_lbox[blk] = v;   // single writer per scale
                else          g_nb[blk]   = v;
            }
        }
    }

    // ---------------- finisher ----------------
    __syncthreads();
    if (tid == 0) {
        __threadfence();
        unsigned old = atomicAdd(&g_done, 1u);
        if (old == NBLK - 1) {
            __threadfence();
            float lboxT = 0.f, lclsT = 0.f;
#pragma unroll
            for (int i = 0; i < 3; i++) {
                float nbv = fmaxf(g_nb[i], 1.0f);
                lboxT += g_lbox[i] / nbv;
                lclsT += g_lcls[i] / (nbv * (float)NC);
            }
            float lobjT = g_obj * 64.3f;
            lboxT *= 3.54f;
            lclsT *= 37.4f;
            out[0] = lboxT + lobjT + lclsT;
            out[1] = lboxT;
            out[2] = lobjT;
            out[3] = lclsT;
            g_obj = 0.f;
#pragma unroll
            for (int i = 0; i < 3; i++) {
                g_lcls[i] = 0.f; g_lbox[i] = 0.f; g_nb[i] = 0.f;
            }
            g_done = 0u;
            __threadfence();
        }
    }
}

extern "C" void kernel_launch(void* const* d_in, const int* in_sizes, int n_in,
                              void* d_out, int out_size) {
    const float* p0         = (const float*)d_in[0];
    const float* p1         = (const float*)d_in[1];
    const float* p2         = (const float*)d_in[2];
    const float* targets    = (const float*)d_in[3];
    const float* anchors    = (const float*)d_in[4];
    const float* image_size = (const float*)d_in[5];
    float* out = (float*)d_out;

    yolo_fused<<<NBLK, NTHR>>>(p0, p1, p2, targets, anchors, image_size, out);
}